// round 15
// baseline (speedup 1.0000x reference)
#include <cuda_runtime.h>

// ---------------- problem constants ----------------
#define TB 64           // batch
#define TT 1024         // time steps
#define TI 64           // input size
#define TH 256          // hidden size
#define NGROUP 4        // independent batch groups
#define CPG 32          // CTAs per group
#define BPG 16          // batches per group
#define NCTA (NGROUP*CPG)
#define NTHR 512
#define K0 320          // layer0 concat [x(64) ; h0_d(256)]
#define K1 768          // layer1 concat [h0cat(512) ; h1_d(256)]
#define SXK 132         // smem x row stride (128 chunk + 4 pad)
#define BP  17          // gates buffer batch stride

// smem partition (floats)
#define OFS_SW0 0
#define OFS_SW1 (48*K0)                       // 15360
#define OFS_SX  (OFS_SW1 + 48*K1)             // 52224 : 2 buffers [16][SXK]
#define OFS_GA  (OFS_SX + 2*16*SXK)           // 56448 : [48 rows][BP]
#define OFS_GB  (OFS_GA + 48*BP)              // 57264 : [16 units][BP]
#define SMEM_FLOATS (OFS_GB + 16*BP)          // 57536 floats = 230144 bytes

// ---------------- device scratch ----------------
__device__ float g_xT[TT * TB * TI];          // [t][b][i]
__device__ float g_h0[2 * TB * 512];          // [parity][b][u]
__device__ float g_h1[2 * TB * 512];
__device__ int      g_bar_count[NGROUP];      // atomic barrier (proven R3/R6/R8)
__device__ unsigned g_bar_gen[NGROUP];        // monotonic generation counter

// ---------------- input transpose ----------------
__global__ void transpose_kernel(const float* __restrict__ x) {
    int idx = blockIdx.x * blockDim.x + threadIdx.x;
    if (idx < TT * TB * TI) {
        int i = idx & 63;
        int b = (idx >> 6) & 63;
        int t = idx >> 12;
        g_xT[idx] = x[(b * TT + t) * TI + i];
    }
}

__device__ __forceinline__ float sigmf(float v) { return 1.0f / (1.0f + __expf(-v)); }
__device__ __forceinline__ float tanh_fast(float v) { return 2.0f / (1.0f + __expf(-2.0f * v)) - 1.0f; }

__device__ __forceinline__ void fma2(unsigned long long& acc,
                                     unsigned long long a, unsigned long long b) {
    asm("fma.rn.f32x2 %0, %1, %2, %0;" : "+l"(acc) : "l"(a), "l"(b));
}

// ---------------- cp.async helpers ----------------
__device__ __forceinline__ void cp16(float* s, const float* g) {
    unsigned ss = (unsigned)__cvta_generic_to_shared(s);
    asm volatile("cp.async.cg.shared.global [%0], [%1], 16;" :: "r"(ss), "l"(g) : "memory");
}
__device__ __forceinline__ void cp_commit() {
    asm volatile("cp.async.commit_group;" ::: "memory");
}
template <int N>
__device__ __forceinline__ void cp_wait() {
    asm volatile("cp.async.wait_group %0;" :: "n"(N) : "memory");
}

// stage CH floats per batch-row (16 rows) via cp.async
template <int CH>
__device__ __forceinline__ void stage_async(float* __restrict__ sx,
                                            const float* __restrict__ src, int srcStride) {
    constexpr int NV = CH / 4;
    for (int idx = threadIdx.x; idx < 16 * NV; idx += NTHR) {
        int bl = idx / NV;
        int kk = idx - bl * NV;
        cp16(sx + bl * SXK + kk * 4, src + bl * srcStride + kk * 4);
    }
    cp_commit();
}

// ---------------- group barrier (atomic, generation-counted; proven) ----------------
__device__ __forceinline__ void group_barrier(int grp, unsigned target) {
    __syncthreads();
    if (threadIdx.x == 0) {
        __threadfence();
        int prev = atomicAdd(&g_bar_count[grp], 1);
        if (prev == CPG - 1) {
            atomicExch(&g_bar_count[grp], 0);
            __threadfence();
            atomicAdd(&g_bar_gen[grp], 1u);
        } else {
            while (atomicAdd(&g_bar_gen[grp], 0u) < target) { }
        }
        __threadfence();
    }
    __syncthreads();
}

// split-K register-tiled accumulation, 512-thread / 3-row-per-warp version.
// warp = row group 0..15 (rows: 2 r/z + 1 n). lane: ks = lane & 7 (8 k-slices),
// cq = lane >> 3 (4 batch-quads covering all 16 batches).
// Lane tile: 3 rows x 4 batches x 4k; one j-iter covers 32 consecutive k.
// Conflict-free: each 8-lane phase (constant cq) reads 8 consecutive 16B = 128B.
template <int ITERS>
__device__ __forceinline__ void accum_chunk(unsigned long long acc[3][4],
                                            const float* __restrict__ wbase, int K,
                                            const float* __restrict__ sx,
                                            int ks, int cq) {
    const float* xb = sx + (cq * 4) * SXK;
#pragma unroll
    for (int j = 0; j < ITERS; ++j) {
        int k4 = (j * 8 + ks) * 4;
        ulonglong2 xv[4];
#pragma unroll
        for (int i = 0; i < 4; ++i)
            xv[i] = *reinterpret_cast<const ulonglong2*>(xb + i * SXK + k4);
        ulonglong2 wv[3];
#pragma unroll
        for (int r = 0; r < 3; ++r)
            wv[r] = *reinterpret_cast<const ulonglong2*>(wbase + r * K + k4);
#pragma unroll
        for (int r = 0; r < 3; ++r)
#pragma unroll
            for (int i = 0; i < 4; ++i) {
                fma2(acc[r][i], wv[r].x, xv[i].x);
                fma2(acc[r][i], wv[r].y, xv[i].y);
            }
    }
}

// fold the n-row (row 2) into sv and reset it (r/z rows keep running)
__device__ __forceinline__ void fold_n(unsigned long long acc[3][4], float sv[4]) {
#pragma unroll
    for (int i = 0; i < 4; ++i) {
        union { unsigned long long u; float2 f; } cv; cv.u = acc[2][i];
        sv[i] = cv.f.x + cv.f.y;
        acc[2][i] = 0ull;
    }
}

// end-of-layer: fold + cross-slice shfl reduction + publish; resets accs.
// saved sv = n-gate I part; live n-row = H part (call order: I-part chunks first,
// fold, then H-part chunks — both layers use this convention below).
__device__ __forceinline__ void reduce_layer(unsigned long long acc[3][4],
                                             const float sv[4],
                                             int w, int lane,
                                             float* __restrict__ GA, float* __restrict__ GB) {
    const int cq = lane >> 3;
    const bool wr = (lane & 7) == 0;
    const int colb = cq * 4;
#pragma unroll
    for (int q = 0; q < 2; ++q) {              // r/z rows (total only)
        int garow = w * 2 + q;                 // rz index == GA row (r:0-15, z:16-31)
#pragma unroll
        for (int i = 0; i < 4; ++i) {
            union { unsigned long long u; float2 f; } cv; cv.u = acc[q][i];
            float s = cv.f.x + cv.f.y;
            acc[q][i] = 0ull;
            s += __shfl_xor_sync(0xffffffffu, s, 1);
            s += __shfl_xor_sync(0xffffffffu, s, 2);
            s += __shfl_xor_sync(0xffffffffu, s, 4);
            if (wr) GA[garow * BP + colb + i] = s;
        }
    }
    // n row: I saved, H live
#pragma unroll
    for (int i = 0; i < 4; ++i) {
        union { unsigned long long u; float2 f; } cv; cv.u = acc[2][i];
        float h = cv.f.x + cv.f.y;             // live = H part
        acc[2][i] = 0ull;
        h += __shfl_xor_sync(0xffffffffu, h, 1);
        h += __shfl_xor_sync(0xffffffffu, h, 2);
        h += __shfl_xor_sync(0xffffffffu, h, 4);
        float s = sv[i];                       // saved = I part
        s += __shfl_xor_sync(0xffffffffu, s, 1);
        s += __shfl_xor_sync(0xffffffffu, s, 2);
        s += __shfl_xor_sync(0xffffffffu, s, 4);
        if (wr) {
            GA[(32 + w) * BP + colb + i] = s;
            GB[w * BP + colb + i] = h;
        }
    }
}

// ---------------- persistent GRU kernel ----------------
__global__ void __launch_bounds__(NTHR, 1) gru_persistent(
    const float* __restrict__ W_ih0, const float* __restrict__ W_hh0,
    const float* __restrict__ b_ih0, const float* __restrict__ b_hh0,
    const float* __restrict__ W_ih1, const float* __restrict__ W_hh1,
    const float* __restrict__ b_ih1, const float* __restrict__ b_hh1,
    const int* __restrict__ seq_len, float* __restrict__ out)
{
    extern __shared__ float smem[];
    float* sw0 = smem + OFS_SW0;   // [48 warp-major rows][K0] (3 rows per warp)
    float* sw1 = smem + OFS_SW1;   // [48][K1]
    float* sx0 = smem + OFS_SX;
    float* sx1 = smem + OFS_SX + 16 * SXK;
    float* GA  = smem + OFS_GA;    // [48][BP]  rows: r(0-15), z(16-31), nI(32-47)
    float* GB  = smem + OFS_GB;    // [16][BP]  nH

    const int tid = threadIdx.x;
    const int cta = blockIdx.x;
    const int grp = cta / CPG;
    const int cg  = cta % CPG;
    const int d     = cg >> 4;
    const int jbase = (cg & 15) * 16;
    const int gb    = grp * BPG;

    const int warp = tid >> 5;           // row group 0..15 (3 rows each)
    const int lane = tid & 31;
    const int ks   = lane & 7;
    const int cq   = lane >> 3;

    const bool act = (tid < 256);        // gate/output-active threads
    const int lu = tid & 15;
    const int b  = tid >> 4;             // valid batch only when act
    const int j  = jbase + lu;
    const int u  = d * TH + j;
    const int me = act ? ((gb + b) * 512 + u) : 0;

    // ---- stage weights into smem (per-warp rows: 2 r/z + 1 n) ----
    // smem row sr = w*3 + q : q<2 -> rz = w*2+q (gate rz>>4, unit rz&15); q==2 -> n unit w
    for (int idx = tid; idx < 48 * K0; idx += NTHR) {
        int k = idx % K0, sr = idx / K0;
        int w = sr / 3, q = sr % 3;
        int gu;
        if (q < 2) { int rz = w * 2 + q; gu = (rz >> 4) * 256 + jbase + (rz & 15); }
        else       { gu = 512 + jbase + w; }
        int grow = d * 768 + gu;
        sw0[idx] = (k < TI) ? W_ih0[grow * TI + k] : W_hh0[grow * TH + (k - TI)];
    }
    for (int idx = tid; idx < 48 * K1; idx += NTHR) {
        int k = idx % K1, sr = idx / K1;
        int w = sr / 3, q = sr % 3;
        int gu;
        if (q < 2) { int rz = w * 2 + q; gu = (rz >> 4) * 256 + jbase + (rz & 15); }
        else       { gu = 512 + jbase + w; }
        int grow = d * 768 + gu;
        sw1[idx] = (k < 512) ? W_ih1[grow * 512 + k] : W_hh1[grow * TH + (k - 512)];
    }

    const int base = d * 768;
    float b0r = 0, b0z = 0, b0ni = 0, b0nh = 0, b1r = 0, b1z = 0, b1ni = 0, b1nh = 0;
    int myidx = 0;
    if (act) {
        b0r = b_ih0[base + j] + b_hh0[base + j];
        b0z = b_ih0[base + TH + j] + b_hh0[base + TH + j];
        b0ni = b_ih0[base + 2 * TH + j];
        b0nh = b_hh0[base + 2 * TH + j];
        b1r = b_ih1[base + j] + b_hh1[base + j];
        b1z = b_ih1[base + TH + j] + b_hh1[base + TH + j];
        b1ni = b_ih1[base + 2 * TH + j];
        b1nh = b_hh1[base + 2 * TH + j];
        myidx = seq_len[gb + b] - 1;
        if (myidx < 0) myidx = 0;
        if (myidx > TT - 1) myidx = TT - 1;
        // zero initial hidden state (parity 0)
        __stcg(&g_h0[me], 0.0f);
        __stcg(&g_h1[me], 0.0f);
    }

    __shared__ unsigned s_genbase;
    if (tid == 0) s_genbase = atomicAdd(&g_bar_gen[grp], 0u);
    __syncthreads();
    const unsigned genbase = s_genbase;
    unsigned nbar = 0;

    nbar++; group_barrier(grp, genbase + nbar);   // zeros + weights visible

    unsigned long long acc[3][4];
#pragma unroll
    for (int r = 0; r < 3; ++r)
#pragma unroll
        for (int i = 0; i < 4; ++i) acc[r][i] = 0ull;

    const float* sw0w = sw0 + warp * 3 * K0;
    const float* sw1w = sw1 + warp * 3 * K1;

    // prologue staging: A0(0) -> sx0, A1(0) -> sx1
    stage_async<64>(sx0, g_xT + gb * TI, TI);
    stage_async<128>(sx1, g_h0 + gb * 512 + d * TH, 512);

    for (int t = 0; t < TT; ++t) {
        const int rp = t & 1, wp = rp ^ 1;
        const float* h0r = g_h0 + rp * (TB * 512);
        float*       h0w = g_h0 + wp * (TB * 512);
        const float* h1r = g_h1 + rp * (TB * 512);
        float*       h1w = g_h1 + wp * (TB * 512);
        float* bA = (t & 1) ? sx1 : sx0;   // slots A0,A2,B1,B3,B5,A1'
        float* bB = (t & 1) ? sx0 : sx1;   // slots A1,B0,B2,B4,A0'

        float sv[4];

        // ================= phase 1 : layer 0  (K = 64 + 256) =================
        float hp0 = act ? __ldcg(h0r + me) : 0.0f;

        // slot A0 (bA): x part            outstanding: [A0, A1]
        cp_wait<1>(); __syncthreads();
        accum_chunk<2>(acc, sw0w, K0, bA, ks, cq);
        fold_n(acc, sv);                                    // sv = nI (layer0)
        __syncthreads();
        stage_async<128>(bA, h0r + gb * 512 + d * TH + 128, 512);   // A2
        // slot A1 (bB): h0_d k 0..127     outstanding: [A1, A2]
        cp_wait<1>(); __syncthreads();
        accum_chunk<4>(acc, sw0w + TI, K0, bB, ks, cq);
        // slot A2 (bA): h0_d k 128..255
        cp_wait<0>(); __syncthreads();
        accum_chunk<4>(acc, sw0w + TI + 128, K0, bA, ks, cq);
        reduce_layer(acc, sv, warp, lane, GA, GB);
        __syncthreads();
        if (act) {
            float aR  = GA[lu * BP + b] + b0r;
            float aZ  = GA[(16 + lu) * BP + b] + b0z;
            float aI  = GA[(32 + lu) * BP + b] + b0ni;
            float aH  = GB[lu * BP + b] + b0nh;
            float r  = sigmf(aR);
            float z  = sigmf(aZ);
            float n  = tanh_fast(aI + r * aH);
            float hn = n + z * (hp0 - n);
            __stcg(h0w + me, hn);
        }

        // single cross-CTA barrier per step: h0(t) published group-wide
        nbar++; group_barrier(grp, genbase + nbar);

        // ================= phase 2 : layer 1  (K = 512 + 256) =================
        float hp1 = act ? __ldcg(h1r + me) : 0.0f;
        stage_async<128>(bB, h0w + gb * 512 + 0,   512);            // B0
        stage_async<128>(bA, h0w + gb * 512 + 128, 512);            // B1

        // slot B0 (bB)
        cp_wait<1>(); __syncthreads();
        accum_chunk<4>(acc, sw1w, K1, bB, ks, cq);
        __syncthreads();
        stage_async<128>(bB, h0w + gb * 512 + 256, 512);            // B2
        // slot B1 (bA)
        cp_wait<1>(); __syncthreads();
        accum_chunk<4>(acc, sw1w + 128, K1, bA, ks, cq);
        __syncthreads();
        stage_async<128>(bA, h0w + gb * 512 + 384, 512);            // B3
        // slot B2 (bB)
        cp_wait<1>(); __syncthreads();
        accum_chunk<4>(acc, sw1w + 256, K1, bB, ks, cq);
        __syncthreads();
        stage_async<128>(bB, h1r + gb * 512 + d * TH, 512);         // B4
        // slot B3 (bA)
        cp_wait<1>(); __syncthreads();
        accum_chunk<4>(acc, sw1w + 384, K1, bA, ks, cq);
        fold_n(acc, sv);                                            // sv = nI (layer1)
        __syncthreads();
        stage_async<128>(bA, h1r + gb * 512 + d * TH + 128, 512);   // B5
        // slot B4 (bB)
        cp_wait<1>(); __syncthreads();
        accum_chunk<4>(acc, sw1w + 512, K1, bB, ks, cq);
        __syncthreads();
        {   // A0(t+1): x prefetch (clamped at sequence end)
            int tt = (t + 1 < TT) ? t + 1 : TT - 1;
            stage_async<64>(bB, g_xT + tt * (TB * TI) + gb * TI, TI);
        }
        // slot B5 (bA)
        cp_wait<1>(); __syncthreads();
        accum_chunk<4>(acc, sw1w + 640, K1, bA, ks, cq);
        __syncthreads();
        stage_async<128>(bA, h0w + gb * 512 + d * TH, 512);         // A1(t+1)
        reduce_layer(acc, sv, warp, lane, GA, GB);
        __syncthreads();
        if (act) {
            float aR  = GA[lu * BP + b] + b1r;
            float aZ  = GA[(16 + lu) * BP + b] + b1z;
            float aI  = GA[(32 + lu) * BP + b] + b1ni;
            float aH  = GB[lu * BP + b] + b1nh;
            float r  = sigmf(aR);
            float z  = sigmf(aZ);
            float n  = tanh_fast(aI + r * aH);
            float hn = n + z * (hp1 - n);
            __stcg(h1w + me, hn);
            if (t == myidx) out[(gb + b) * (2 * TH) + u] = hn;
        }
    }

    cp_wait<0>();      // drain the speculative t=TT stages
    __syncthreads();
}

// ---------------- launch ----------------
extern "C" void kernel_launch(void* const* d_in, const int* in_sizes, int n_in,
                              void* d_out, int out_size) {
    const float* x     = (const float*)d_in[0];
    const float* W_ih0 = (const float*)d_in[1];
    const float* W_hh0 = (const float*)d_in[2];
    const float* b_ih0 = (const float*)d_in[3];
    const float* b_hh0 = (const float*)d_in[4];
    const float* W_ih1 = (const float*)d_in[5];
    const float* W_hh1 = (const float*)d_in[6];
    const float* b_ih1 = (const float*)d_in[7];
    const float* b_hh1 = (const float*)d_in[8];
    const int*   seqlv = (const int*)d_in[9];
    float* out = (float*)d_out;

    const size_t SMEM_BYTES = (size_t)SMEM_FLOATS * sizeof(float);
    cudaFuncSetAttribute(gru_persistent, cudaFuncAttributeMaxDynamicSharedMemorySize,
                         (int)SMEM_BYTES);

    transpose_kernel<<<(TT * TB * TI + 255) / 256, 256>>>(x);
    gru_persistent<<<NCTA, NTHR, SMEM_BYTES>>>(W_ih0, W_hh0, b_ih0, b_hh0,
                                               W_ih1, W_hh1, b_ih1, b_hh1,
                                               seqlv, out);
}

// round 16
// speedup vs baseline: 1.1001x; 1.1001x over previous
#include <cuda_runtime.h>

// ---------------- problem constants ----------------
#define TB 64           // batch
#define TT 1024         // time steps
#define TI 64           // input size
#define TH 256          // hidden size
#define NGROUP 4        // independent batch groups
#define CPG 32          // CTAs per group
#define BPG 16          // batches per group
#define NCTA (NGROUP*CPG)
#define NTHR 256
#define K0 320          // layer0 concat [x(64) ; h0_d(256)]
#define K1 768          // layer1 concat [h0cat(512) ; h1_d(256)]
#define BP  17          // gates buffer batch stride

// smem partition (floats): weights + gate buffers ONLY (no staging buffers)
#define OFS_SW0 0
#define OFS_SW1 (48*K0)                       // 15360
#define OFS_GA  (OFS_SW1 + 48*K1)             // 52224 : [48 rows][BP]
#define OFS_GB  (OFS_GA + 48*BP)              // 53040 : [16][BP]
#define SMEM_FLOATS (OFS_GB + 16*BP)          // 53312 floats = 213,248 bytes

// ---------------- device scratch ----------------
__device__ float g_xT[TT * TB * TI];          // [t][b][i]
__device__ float g_h0[2 * TB * 512];          // [parity][b][u]
__device__ float g_h1[2 * TB * 512];
__device__ int      g_bar_count[NGROUP];      // atomic barrier (proven R3/R6/R8)
__device__ unsigned g_bar_gen[NGROUP];        // monotonic generation counter

// ---------------- input transpose ----------------
__global__ void transpose_kernel(const float* __restrict__ x) {
    int idx = blockIdx.x * blockDim.x + threadIdx.x;
    if (idx < TT * TB * TI) {
        int i = idx & 63;
        int b = (idx >> 6) & 63;
        int t = idx >> 12;
        g_xT[idx] = x[(b * TT + t) * TI + i];
    }
}

__device__ __forceinline__ float sigmf(float v) { return 1.0f / (1.0f + __expf(-v)); }
__device__ __forceinline__ float tanh_fast(float v) { return 2.0f / (1.0f + __expf(-2.0f * v)) - 1.0f; }

__device__ __forceinline__ void fma2(unsigned long long& acc,
                                     unsigned long long a, unsigned long long b) {
    asm("fma.rn.f32x2 %0, %1, %2, %0;" : "+l"(acc) : "l"(a), "l"(b));
}

// 16B L2 (non-L1-polluting) load
__device__ __forceinline__ ulonglong2 ldg2(const float* g) {
    ulonglong2 v;
    asm volatile("ld.global.cg.v2.u64 {%0, %1}, [%2];"
                 : "=l"(v.x), "=l"(v.y) : "l"(g));
    return v;
}

// ---------------- group barrier (atomic, generation-counted; proven) ----------------
__device__ __forceinline__ void group_barrier(int grp, unsigned target) {
    __syncthreads();
    if (threadIdx.x == 0) {
        __threadfence();
        int prev = atomicAdd(&g_bar_count[grp], 1);
        if (prev == CPG - 1) {
            atomicExch(&g_bar_count[grp], 0);
            __threadfence();
            atomicAdd(&g_bar_gen[grp], 1u);
        } else {
            while (atomicAdd(&g_bar_gen[grp], 0u) < target) { }
        }
        __threadfence();
    }
    __syncthreads();
}

// ---------------- register-tiled accumulation, operands direct from L2 ----------------
// lane: ks = lane & 15 (16 k-slices), c = lane >> 4 (2 batch-octets).
// Lane tile: 6 rows x 8 batches x 4k. One j-iter covers 64 consecutive k.
// xv: LDG.128 from gsrc (row stride STRIDE floats) — per warp-LDG: 2 batches x 256B, coalesced.
// wv: LDS.128 from smem weights (broadcast across octets, conflict-free).
// acc rows 0..3 = r/z (I+H merged), rows 4..5 = n.
template <int ITERS, int STRIDE>
__device__ __forceinline__ void accum_g(unsigned long long acc[6][8],
                                        const float* __restrict__ wbase, int K,
                                        const float* __restrict__ gsrc,
                                        int ks, int c) {
    const float* xb = gsrc + (c * 8) * STRIDE;
#pragma unroll
    for (int j = 0; j < ITERS; ++j) {
        int k4 = (j * 16 + ks) * 4;
        ulonglong2 xv[8];
#pragma unroll
        for (int i = 0; i < 8; ++i)
            xv[i] = ldg2(xb + i * STRIDE + k4);
        ulonglong2 wv[6];
#pragma unroll
        for (int r = 0; r < 6; ++r)
            wv[r] = *reinterpret_cast<const ulonglong2*>(wbase + r * K + k4);
#pragma unroll
        for (int r = 0; r < 6; ++r)
#pragma unroll
            for (int i = 0; i < 8; ++i) {
                fma2(acc[r][i], wv[r].x, xv[i].x);
                fma2(acc[r][i], wv[r].y, xv[i].y);
            }
    }
}

// fold n-rows (4,5) into sv and reset them (r/z rows keep running)
__device__ __forceinline__ void fold_n(unsigned long long acc[6][8], float sv[2][8]) {
#pragma unroll
    for (int q = 0; q < 2; ++q)
#pragma unroll
        for (int i = 0; i < 8; ++i) {
            union { unsigned long long u; float2 f; } cv; cv.u = acc[4 + q][i];
            sv[q][i] = cv.f.x + cv.f.y;
            acc[4 + q][i] = 0ull;
        }
}

// end-of-layer: fold + cross-slice shfl reduction + publish; resets accs.
// Convention (both layers): I-part computed first -> fold -> sv = nI (saved);
// live n-rows at reduce time = nH.
__device__ __forceinline__ void reduce_layer(unsigned long long acc[6][8],
                                             const float sv[2][8],
                                             int w, int lane,
                                             float* __restrict__ GA, float* __restrict__ GB) {
    const int c = lane >> 4;
    const bool wr = (lane & 15) == 0;
#pragma unroll
    for (int q = 0; q < 4; ++q) {              // r/z rows (total only)
        int garow = w * 4 + q;
#pragma unroll
        for (int i = 0; i < 8; ++i) {
            union { unsigned long long u; float2 f; } cv; cv.u = acc[q][i];
            float s = cv.f.x + cv.f.y;
            acc[q][i] = 0ull;
            s += __shfl_xor_sync(0xffffffffu, s, 1);
            s += __shfl_xor_sync(0xffffffffu, s, 2);
            s += __shfl_xor_sync(0xffffffffu, s, 4);
            s += __shfl_xor_sync(0xffffffffu, s, 8);
            if (wr) GA[garow * BP + c * 8 + i] = s;
        }
    }
#pragma unroll
    for (int q = 0; q < 2; ++q) {              // n rows (saved=I, live=H)
        int nn = w * 2 + q;
#pragma unroll
        for (int i = 0; i < 8; ++i) {
            union { unsigned long long u; float2 f; } cv; cv.u = acc[4 + q][i];
            float h = cv.f.x + cv.f.y;         // live = H part
            acc[4 + q][i] = 0ull;
            h += __shfl_xor_sync(0xffffffffu, h, 1);
            h += __shfl_xor_sync(0xffffffffu, h, 2);
            h += __shfl_xor_sync(0xffffffffu, h, 4);
            h += __shfl_xor_sync(0xffffffffu, h, 8);
            float s = sv[q][i];                // saved = I part
            s += __shfl_xor_sync(0xffffffffu, s, 1);
            s += __shfl_xor_sync(0xffffffffu, s, 2);
            s += __shfl_xor_sync(0xffffffffu, s, 4);
            s += __shfl_xor_sync(0xffffffffu, s, 8);
            if (wr) {
                GA[(32 + nn) * BP + c * 8 + i] = s;
                GB[nn * BP + c * 8 + i] = h;
            }
        }
    }
}

// ---------------- persistent GRU kernel ----------------
__global__ void __launch_bounds__(NTHR, 1) gru_persistent(
    const float* __restrict__ W_ih0, const float* __restrict__ W_hh0,
    const float* __restrict__ b_ih0, const float* __restrict__ b_hh0,
    const float* __restrict__ W_ih1, const float* __restrict__ W_hh1,
    const float* __restrict__ b_ih1, const float* __restrict__ b_hh1,
    const int* __restrict__ seq_len, float* __restrict__ out)
{
    extern __shared__ float smem[];
    float* sw0 = smem + OFS_SW0;   // [48 warp-major rows][K0] (4 r/z + 2 n per warp)
    float* sw1 = smem + OFS_SW1;   // [48][K1]
    float* GA  = smem + OFS_GA;    // [48][BP]  rows: r(0-15), z(16-31), nI(32-47)
    float* GB  = smem + OFS_GB;    // [16][BP]  nH

    const int tid = threadIdx.x;
    const int cta = blockIdx.x;
    const int grp = cta / CPG;
    const int cg  = cta % CPG;
    const int d     = cg >> 4;
    const int jbase = (cg & 15) * 16;
    const int gb    = grp * BPG;

    const int warp = tid >> 5;
    const int lane = tid & 31;
    const int ks   = lane & 15;
    const int c    = lane >> 4;

    const int lu = tid & 15;
    const int b  = tid >> 4;
    const int j  = jbase + lu;
    const int u  = d * TH + j;
    const int me = (gb + b) * 512 + u;

    // ---- stage weights into smem (warp-major rows: 4 r/z + 2 n per warp) ----
    for (int idx = tid; idx < 48 * K0; idx += NTHR) {
        int k = idx % K0, sr = idx / K0;
        int w = sr / 6, q = sr % 6;
        int gu;
        if (q < 4) { int rz = w * 4 + q; gu = (rz >> 4) * 256 + jbase + (rz & 15); }
        else       { int nn = w * 2 + (q - 4); gu = 512 + jbase + nn; }
        int grow = d * 768 + gu;
        sw0[idx] = (k < TI) ? W_ih0[grow * TI + k] : W_hh0[grow * TH + (k - TI)];
    }
    for (int idx = tid; idx < 48 * K1; idx += NTHR) {
        int k = idx % K1, sr = idx / K1;
        int w = sr / 6, q = sr % 6;
        int gu;
        if (q < 4) { int rz = w * 4 + q; gu = (rz >> 4) * 256 + jbase + (rz & 15); }
        else       { int nn = w * 2 + (q - 4); gu = 512 + jbase + nn; }
        int grow = d * 768 + gu;
        sw1[idx] = (k < 512) ? W_ih1[grow * 512 + k] : W_hh1[grow * TH + (k - 512)];
    }

    const int base = d * 768;
    const float b0r = b_ih0[base + j] + b_hh0[base + j];
    const float b0z = b_ih0[base + TH + j] + b_hh0[base + TH + j];
    const float b0ni = b_ih0[base + 2 * TH + j];
    const float b0nh = b_hh0[base + 2 * TH + j];
    const float b1r = b_ih1[base + j] + b_hh1[base + j];
    const float b1z = b_ih1[base + TH + j] + b_hh1[base + TH + j];
    const float b1ni = b_ih1[base + 2 * TH + j];
    const float b1nh = b_hh1[base + 2 * TH + j];

    int myidx = seq_len[gb + b] - 1;
    if (myidx < 0) myidx = 0;
    if (myidx > TT - 1) myidx = TT - 1;

    // zero initial hidden state (parity 0)
    __stcg(&g_h0[me], 0.0f);
    __stcg(&g_h1[me], 0.0f);

    __shared__ unsigned s_genbase;
    if (tid == 0) s_genbase = atomicAdd(&g_bar_gen[grp], 0u);
    __syncthreads();
    const unsigned genbase = s_genbase;
    unsigned nbar = 0;

    nbar++; group_barrier(grp, genbase + nbar);   // zeros + weights visible

    unsigned long long acc[6][8];
#pragma unroll
    for (int r = 0; r < 6; ++r)
#pragma unroll
        for (int i = 0; i < 8; ++i) acc[r][i] = 0ull;

    const float* sw0w = sw0 + warp * 6 * K0;
    const float* sw1w = sw1 + warp * 6 * K1;

    for (int t = 0; t < TT; ++t) {
        const int rp = t & 1, wp = rp ^ 1;
        const float* h0r = g_h0 + rp * (TB * 512);
        float*       h0w = g_h0 + wp * (TB * 512);
        const float* h1r = g_h1 + rp * (TB * 512);
        float*       h1w = g_h1 + wp * (TB * 512);

        float sv[2][8];

        // ================= phase 1 : layer 0  (K = 64 + 256) =================
        float hp0 = __ldcg(h0r + me);
        float hp1 = __ldcg(h1r + me);

        // x part (I) straight from L2, then fold -> sv = nI
        accum_g<1, TI>(acc, sw0w, K0, g_xT + t * (TB * TI) + gb * TI, ks, c);
        fold_n(acc, sv);
        // hidden part (H): h0_d (256) straight from L2
        accum_g<4, 512>(acc, sw0w + TI, K0, h0r + gb * 512 + d * TH, ks, c);

        __syncthreads();                       // prior GA/GB readers done
        reduce_layer(acc, sv, warp, lane, GA, GB);
        __syncthreads();                       // GA/GB visible
        {
            float aR  = GA[lu * BP + b] + b0r;
            float aZ  = GA[(16 + lu) * BP + b] + b0z;
            float aI  = GA[(32 + lu) * BP + b] + b0ni;
            float aH  = GB[lu * BP + b] + b0nh;
            float r  = sigmf(aR);
            float z  = sigmf(aZ);
            float n  = tanh_fast(aI + r * aH);
            float hn = n + z * (hp0 - n);
            __stcg(h0w + me, hn);
        }

        // single cross-CTA barrier per step: h0(t) published group-wide
        nbar++; group_barrier(grp, genbase + nbar);

        // ================= phase 2 : layer 1  (K = 512 + 256) =================
        // I part: h0(t) full concat (512), straight from L2 (post-barrier)
        accum_g<4, 512>(acc, sw1w,       K1, h0w + gb * 512,       ks, c);
        accum_g<4, 512>(acc, sw1w + 256, K1, h0w + gb * 512 + 256, ks, c);
        fold_n(acc, sv);                       // sv = nI
        // H part: h1(t-1)_d (256)
        accum_g<4, 512>(acc, sw1w + 512, K1, h1r + gb * 512 + d * TH, ks, c);

        __syncthreads();                       // prior GA/GB readers done
        reduce_layer(acc, sv, warp, lane, GA, GB);
        __syncthreads();                       // GA/GB visible
        {
            float aR  = GA[lu * BP + b] + b1r;
            float aZ  = GA[(16 + lu) * BP + b] + b1z;
            float aI  = GA[(32 + lu) * BP + b] + b1ni;
            float aH  = GB[lu * BP + b] + b1nh;
            float r  = sigmf(aR);
            float z  = sigmf(aZ);
            float n  = tanh_fast(aI + r * aH);
            float hn = n + z * (hp1 - n);
            __stcg(h1w + me, hn);
            if (t == myidx) out[(gb + b) * (2 * TH) + u] = hn;
        }
        // next phase1 reads h0(t) (parity flip) — published by this step's barrier;
        // h1(t) cross-CTA reads happen in phase2(t+1), after barrier(t+1). Proven
        // ordering identical to R8 (arrival at barrier(t+1) implies phase2(t) done).
    }
}

// ---------------- launch ----------------
extern "C" void kernel_launch(void* const* d_in, const int* in_sizes, int n_in,
                              void* d_out, int out_size) {
    const float* x     = (const float*)d_in[0];
    const float* W_ih0 = (const float*)d_in[1];
    const float* W_hh0 = (const float*)d_in[2];
    const float* b_ih0 = (const float*)d_in[3];
    const float* b_hh0 = (const float*)d_in[4];
    const float* W_ih1 = (const float*)d_in[5];
    const float* W_hh1 = (const float*)d_in[6];
    const float* b_ih1 = (const float*)d_in[7];
    const float* b_hh1 = (const float*)d_in[8];
    const int*   seqlv = (const int*)d_in[9];
    float* out = (float*)d_out;

    const size_t SMEM_BYTES = (size_t)SMEM_FLOATS * sizeof(float);
    cudaFuncSetAttribute(gru_persistent, cudaFuncAttributeMaxDynamicSharedMemorySize,
                         (int)SMEM_BYTES);

    transpose_kernel<<<(TT * TB * TI + 255) / 256, 256>>>(x);
    gru_persistent<<<NCTA, NTHR, SMEM_BYTES>>>(W_ih0, W_hh0, b_ih0, b_hh0,
                                               W_ih1, W_hh1, b_ih1, b_hh1,
                                               seqlv, out);
}

// round 17
// speedup vs baseline: 1.1992x; 1.0901x over previous
#include <cuda_runtime.h>

// ---------------- problem constants ----------------
#define TB 64           // batch
#define TT 1024         // time steps
#define TI 64           // input size
#define TH 256          // hidden size
#define NGROUP 4        // independent batch groups
#define CPG 32          // CTAs per group
#define BPG 16          // batches per group
#define NCTA (NGROUP*CPG)
#define NTHR 256
#define K0 320          // layer0 concat [x(64) ; h0_d(256)]
#define K1 768          // layer1 concat [h0cat(512) ; h1_d(256)]
#define BP  17          // gates buffer batch stride

// smem partition (floats): weights + gate buffers ONLY
#define OFS_SW0 0
#define OFS_SW1 (48*K0)                       // 15360
#define OFS_GA  (OFS_SW1 + 48*K1)             // 52224 : [48 rows][BP]
#define OFS_GB  (OFS_GA + 48*BP)              // 53040 : [16][BP]
#define SMEM_FLOATS (OFS_GB + 16*BP)          // 53312 floats = 213,248 bytes

// ---------------- device scratch ----------------
__device__ float g_xT[TT * TB * TI];          // [t][b][i]
__device__ float g_h0[2 * TB * 512];          // [parity][b][u]
__device__ float g_h1[2 * TB * 512];
__device__ int      g_bar_count[NGROUP];      // atomic barrier (proven)
__device__ unsigned g_bar_gen[NGROUP];        // monotonic generation counter

// ---------------- input transpose ----------------
__global__ void transpose_kernel(const float* __restrict__ x) {
    int idx = blockIdx.x * blockDim.x + threadIdx.x;
    if (idx < TT * TB * TI) {
        int i = idx & 63;
        int b = (idx >> 6) & 63;
        int t = idx >> 12;
        g_xT[idx] = x[(b * TT + t) * TI + i];
    }
}

__device__ __forceinline__ float sigmf(float v) { return 1.0f / (1.0f + __expf(-v)); }
__device__ __forceinline__ float tanh_fast(float v) { return 2.0f / (1.0f + __expf(-2.0f * v)) - 1.0f; }

__device__ __forceinline__ void fma2(unsigned long long& acc,
                                     unsigned long long a, unsigned long long b) {
    asm("fma.rn.f32x2 %0, %1, %2, %0;" : "+l"(acc) : "l"(a), "l"(b));
}

// 16B L2 (non-L1-polluting) load
__device__ __forceinline__ ulonglong2 ldg2(const float* g) {
    ulonglong2 v;
    asm volatile("ld.global.cg.v2.u64 {%0, %1}, [%2];"
                 : "=l"(v.x), "=l"(v.y) : "l"(g));
    return v;
}

// ---------------- group barrier (atomic, generation-counted; proven) ----------------
__device__ __forceinline__ void group_barrier(int grp, unsigned target) {
    __syncthreads();
    if (threadIdx.x == 0) {
        __threadfence();
        int prev = atomicAdd(&g_bar_count[grp], 1);
        if (prev == CPG - 1) {
            atomicExch(&g_bar_count[grp], 0);
            __threadfence();
            atomicAdd(&g_bar_gen[grp], 1u);
        } else {
            while (atomicAdd(&g_bar_gen[grp], 0u) < target) { }
        }
        __threadfence();
    }
    __syncthreads();
}

// ---------------- register chunk pipeline ----------------
// lane map: ks = lane & 7 (8 k-slices x 4 floats = 32k per j-iter),
//           c  = lane >> 3 (4 batch-quads). Lane tile: 6 rows x 4 batches.
// A chunk = 64 consecutive k = 2 j-iters; its operands (8 x 16B) live in registers.
struct XChunk { ulonglong2 v[8]; };

template <int STRIDE>
__device__ __forceinline__ void load_chunk(XChunk& ch, const float* __restrict__ gsrc,
                                           int ks, int c) {
    const float* xb = gsrc + (c * 4) * STRIDE;
#pragma unroll
    for (int jj = 0; jj < 2; ++jj)
#pragma unroll
        for (int i = 0; i < 4; ++i)
            ch.v[jj * 4 + i] = ldg2(xb + i * STRIDE + (jj * 8 + ks) * 4);
}

// consume a chunk: weights (wbase pre-offset to this 64-k window) from smem
__device__ __forceinline__ void fma_chunk(unsigned long long acc[6][4],
                                          const float* __restrict__ wbase, int K,
                                          const XChunk& ch, int ks) {
#pragma unroll
    for (int jj = 0; jj < 2; ++jj) {
        int k4 = (jj * 8 + ks) * 4;
        ulonglong2 wv[6];
#pragma unroll
        for (int r = 0; r < 6; ++r)
            wv[r] = *reinterpret_cast<const ulonglong2*>(wbase + r * K + k4);
#pragma unroll
        for (int r = 0; r < 6; ++r)
#pragma unroll
            for (int i = 0; i < 4; ++i) {
                fma2(acc[r][i], wv[r].x, ch.v[jj * 4 + i].x);
                fma2(acc[r][i], wv[r].y, ch.v[jj * 4 + i].y);
            }
    }
}

// fold n-rows (4,5) into sv and reset them (r/z rows keep running)
__device__ __forceinline__ void fold_n(unsigned long long acc[6][4], float sv[2][4]) {
#pragma unroll
    for (int q = 0; q < 2; ++q)
#pragma unroll
        for (int i = 0; i < 4; ++i) {
            union { unsigned long long u; float2 f; } cv; cv.u = acc[4 + q][i];
            sv[q][i] = cv.f.x + cv.f.y;
            acc[4 + q][i] = 0ull;
        }
}

// end-of-layer: fold + cross-slice shfl reduction + publish; resets accs.
// Convention (both layers): I part first -> fold -> sv = nI; live n-rows = nH.
__device__ __forceinline__ void reduce_layer(unsigned long long acc[6][4],
                                             const float sv[2][4],
                                             int w, int lane,
                                             float* __restrict__ GA, float* __restrict__ GB) {
    const int c = lane >> 3;
    const bool wr = (lane & 7) == 0;
    const int colb = c * 4;
#pragma unroll
    for (int q = 0; q < 4; ++q) {              // r/z rows (total only)
        int garow = w * 4 + q;
#pragma unroll
        for (int i = 0; i < 4; ++i) {
            union { unsigned long long u; float2 f; } cv; cv.u = acc[q][i];
            float s = cv.f.x + cv.f.y;
            acc[q][i] = 0ull;
            s += __shfl_xor_sync(0xffffffffu, s, 1);
            s += __shfl_xor_sync(0xffffffffu, s, 2);
            s += __shfl_xor_sync(0xffffffffu, s, 4);
            if (wr) GA[garow * BP + colb + i] = s;
        }
    }
#pragma unroll
    for (int q = 0; q < 2; ++q) {              // n rows (saved=I, live=H)
        int nn = w * 2 + q;
#pragma unroll
        for (int i = 0; i < 4; ++i) {
            union { unsigned long long u; float2 f; } cv; cv.u = acc[4 + q][i];
            float h = cv.f.x + cv.f.y;         // live = H part
            acc[4 + q][i] = 0ull;
            h += __shfl_xor_sync(0xffffffffu, h, 1);
            h += __shfl_xor_sync(0xffffffffu, h, 2);
            h += __shfl_xor_sync(0xffffffffu, h, 4);
            float s = sv[q][i];                // saved = I part
            s += __shfl_xor_sync(0xffffffffu, s, 1);
            s += __shfl_xor_sync(0xffffffffu, s, 2);
            s += __shfl_xor_sync(0xffffffffu, s, 4);
            if (wr) {
                GA[(32 + nn) * BP + colb + i] = s;
                GB[nn * BP + colb + i] = h;
            }
        }
    }
}

// ---------------- persistent GRU kernel ----------------
__global__ void __launch_bounds__(NTHR, 1) gru_persistent(
    const float* __restrict__ W_ih0, const float* __restrict__ W_hh0,
    const float* __restrict__ b_ih0, const float* __restrict__ b_hh0,
    const float* __restrict__ W_ih1, const float* __restrict__ W_hh1,
    const float* __restrict__ b_ih1, const float* __restrict__ b_hh1,
    const int* __restrict__ seq_len, float* __restrict__ out)
{
    extern __shared__ float smem[];
    float* sw0 = smem + OFS_SW0;   // [48 warp-major rows][K0] (4 r/z + 2 n per warp)
    float* sw1 = smem + OFS_SW1;   // [48][K1]
    float* GA  = smem + OFS_GA;    // [48][BP]  rows: r(0-15), z(16-31), nI(32-47)
    float* GB  = smem + OFS_GB;    // [16][BP]  nH

    const int tid = threadIdx.x;
    const int cta = blockIdx.x;
    const int grp = cta / CPG;
    const int cg  = cta % CPG;
    const int d     = cg >> 4;
    const int jbase = (cg & 15) * 16;
    const int gb    = grp * BPG;

    const int warp = tid >> 5;
    const int lane = tid & 31;
    const int ks   = lane & 7;
    const int c    = lane >> 3;

    const int lu = tid & 15;
    const int b  = tid >> 4;
    const int j  = jbase + lu;
    const int u  = d * TH + j;
    const int me = (gb + b) * 512 + u;

    // ---- stage weights into smem (warp-major rows: 4 r/z + 2 n per warp) ----
    for (int idx = tid; idx < 48 * K0; idx += NTHR) {
        int k = idx % K0, sr = idx / K0;
        int w = sr / 6, q = sr % 6;
        int gu;
        if (q < 4) { int rz = w * 4 + q; gu = (rz >> 4) * 256 + jbase + (rz & 15); }
        else       { int nn = w * 2 + (q - 4); gu = 512 + jbase + nn; }
        int grow = d * 768 + gu;
        sw0[idx] = (k < TI) ? W_ih0[grow * TI + k] : W_hh0[grow * TH + (k - TI)];
    }
    for (int idx = tid; idx < 48 * K1; idx += NTHR) {
        int k = idx % K1, sr = idx / K1;
        int w = sr / 6, q = sr % 6;
        int gu;
        if (q < 4) { int rz = w * 4 + q; gu = (rz >> 4) * 256 + jbase + (rz & 15); }
        else       { int nn = w * 2 + (q - 4); gu = 512 + jbase + nn; }
        int grow = d * 768 + gu;
        sw1[idx] = (k < 512) ? W_ih1[grow * 512 + k] : W_hh1[grow * TH + (k - 512)];
    }

    const int base = d * 768;
    const float b0r = b_ih0[base + j] + b_hh0[base + j];
    const float b0z = b_ih0[base + TH + j] + b_hh0[base + TH + j];
    const float b0ni = b_ih0[base + 2 * TH + j];
    const float b0nh = b_hh0[base + 2 * TH + j];
    const float b1r = b_ih1[base + j] + b_hh1[base + j];
    const float b1z = b_ih1[base + TH + j] + b_hh1[base + TH + j];
    const float b1ni = b_ih1[base + 2 * TH + j];
    const float b1nh = b_hh1[base + 2 * TH + j];

    int myidx = seq_len[gb + b] - 1;
    if (myidx < 0) myidx = 0;
    if (myidx > TT - 1) myidx = TT - 1;

    // zero initial hidden state (parity 0)
    __stcg(&g_h0[me], 0.0f);
    __stcg(&g_h1[me], 0.0f);

    __shared__ unsigned s_genbase;
    if (tid == 0) s_genbase = atomicAdd(&g_bar_gen[grp], 0u);
    __syncthreads();
    const unsigned genbase = s_genbase;
    unsigned nbar = 0;

    nbar++; group_barrier(grp, genbase + nbar);   // zeros + weights visible

    unsigned long long acc[6][4];
#pragma unroll
    for (int r = 0; r < 6; ++r)
#pragma unroll
        for (int i = 0; i < 4; ++i) acc[r][i] = 0ull;

    const float* sw0w = sw0 + warp * 6 * K0;
    const float* sw1w = sw1 + warp * 6 * K1;

    XChunk A, B;
    // prologue: A = x(0), B = h0(0) chunk0 (zeros, published by barrier)
    load_chunk<TI>(A, g_xT + gb * TI, ks, c);
    load_chunk<512>(B, g_h0 + gb * 512 + d * TH, ks, c);

    for (int t = 0; t < TT; ++t) {
        const int rp = t & 1, wp = rp ^ 1;
        const float* h0r = g_h0 + rp * (TB * 512);
        float*       h0w = g_h0 + wp * (TB * 512);
        const float* h1r = g_h1 + rp * (TB * 512);
        float*       h1w = g_h1 + wp * (TB * 512);
        const float* h0rg = h0r + gb * 512 + d * TH;   // this dir's h0 (read)
        const float* h1rg = h1r + gb * 512 + d * TH;   // this dir's h1 (read)
        const float* h0cat = h0w + gb * 512;           // layer1 input (post-barrier)

        float sv[2][4];
        float hp0 = __ldcg(h0r + me);
        float hp1 = __ldcg(h1r + me);

        // ================= phase 1 : layer 0 =================
        // A = x(t) [prefetched], B = h0c0 [prefetched]
        fma_chunk(acc, sw0w, K0, A, ks);               // x part (I)
        fold_n(acc, sv);                               // sv = nI
        load_chunk<512>(A, h0rg + 64, ks, c);          // h0c1
        fma_chunk(acc, sw0w + TI, K0, B, ks);          // h0c0
        load_chunk<512>(B, h0rg + 128, ks, c);         // h0c2
        fma_chunk(acc, sw0w + TI + 64, K0, A, ks);     // h0c1
        load_chunk<512>(A, h0rg + 192, ks, c);         // h0c3
        fma_chunk(acc, sw0w + TI + 128, K0, B, ks);    // h0c2
        fma_chunk(acc, sw0w + TI + 192, K0, A, ks);    // h0c3

        __syncthreads();                               // prior GA/GB readers done
        reduce_layer(acc, sv, warp, lane, GA, GB);
        __syncthreads();                               // GA/GB visible
        {
            float aR  = GA[lu * BP + b] + b0r;
            float aZ  = GA[(16 + lu) * BP + b] + b0z;
            float aI  = GA[(32 + lu) * BP + b] + b0ni;
            float aH  = GB[lu * BP + b] + b0nh;
            float r  = sigmf(aR);
            float z  = sigmf(aZ);
            float n  = tanh_fast(aI + r * aH);
            float hn = n + z * (hp0 - n);
            __stcg(h0w + me, hn);
        }

        // single cross-CTA barrier per step: h0(t) published group-wide
        nbar++; group_barrier(grp, genbase + nbar);

        // ================= phase 2 : layer 1 =================
        // h0cat chunks g0..g7 (I part), then h1_d m0..m3 (H part)
        load_chunk<512>(A, h0cat + 0,   ks, c);        // g0
        load_chunk<512>(B, h0cat + 64,  ks, c);        // g1
        fma_chunk(acc, sw1w, K1, A, ks);               // g0
        load_chunk<512>(A, h0cat + 128, ks, c);        // g2
        fma_chunk(acc, sw1w + 64, K1, B, ks);          // g1
        load_chunk<512>(B, h0cat + 192, ks, c);        // g3
        fma_chunk(acc, sw1w + 128, K1, A, ks);         // g2
        load_chunk<512>(A, h0cat + 256, ks, c);        // g4
        fma_chunk(acc, sw1w + 192, K1, B, ks);         // g3
        load_chunk<512>(B, h0cat + 320, ks, c);        // g5
        fma_chunk(acc, sw1w + 256, K1, A, ks);         // g4
        load_chunk<512>(A, h0cat + 384, ks, c);        // g6
        fma_chunk(acc, sw1w + 320, K1, B, ks);         // g5
        load_chunk<512>(B, h0cat + 448, ks, c);        // g7
        fma_chunk(acc, sw1w + 384, K1, A, ks);         // g6
        load_chunk<512>(A, h1rg + 0, ks, c);           // m0
        fma_chunk(acc, sw1w + 448, K1, B, ks);         // g7
        fold_n(acc, sv);                               // sv = nI
        load_chunk<512>(B, h1rg + 64, ks, c);          // m1
        fma_chunk(acc, sw1w + 512, K1, A, ks);         // m0
        load_chunk<512>(A, h1rg + 128, ks, c);         // m2
        fma_chunk(acc, sw1w + 576, K1, B, ks);         // m1
        load_chunk<512>(B, h1rg + 192, ks, c);         // m3
        fma_chunk(acc, sw1w + 640, K1, A, ks);         // m2
        {   // prefetch next step's phase-1 operands (h0(t) was published by barrier(t))
            int tt = (t + 1 < TT) ? t + 1 : TT - 1;
            load_chunk<TI>(A, g_xT + tt * (TB * TI) + gb * TI, ks, c);   // x(t+1)
        }
        fma_chunk(acc, sw1w + 704, K1, B, ks);         // m3
        load_chunk<512>(B, h0w + gb * 512 + d * TH, ks, c);              // h0c0(t+1)

        __syncthreads();                               // prior GA/GB readers done
        reduce_layer(acc, sv, warp, lane, GA, GB);
        __syncthreads();                               // GA/GB visible
        {
            float aR  = GA[lu * BP + b] + b1r;
            float aZ  = GA[(16 + lu) * BP + b] + b1z;
            float aI  = GA[(32 + lu) * BP + b] + b1ni;
            float aH  = GB[lu * BP + b] + b1nh;
            float r  = sigmf(aR);
            float z  = sigmf(aZ);
            float n  = tanh_fast(aI + r * aH);
            float hn = n + z * (hp1 - n);
            __stcg(h1w + me, hn);
            if (t == myidx) out[(gb + b) * (2 * TH) + u] = hn;
        }
        // h1(t) cross-CTA reads happen in phase2(t+1) after barrier(t+1) — safe
        // (arrival at barrier(t+1) implies phase2(t) complete; proven R8 ordering).
    }
}

// ---------------- launch ----------------
extern "C" void kernel_launch(void* const* d_in, const int* in_sizes, int n_in,
                              void* d_out, int out_size) {
    const float* x     = (const float*)d_in[0];
    const float* W_ih0 = (const float*)d_in[1];
    const float* W_hh0 = (const float*)d_in[2];
    const float* b_ih0 = (const float*)d_in[3];
    const float* b_hh0 = (const float*)d_in[4];
    const float* W_ih1 = (const float*)d_in[5];
    const float* W_hh1 = (const float*)d_in[6];
    const float* b_ih1 = (const float*)d_in[7];
    const float* b_hh1 = (const float*)d_in[8];
    const int*   seqlv = (const int*)d_in[9];
    float* out = (float*)d_out;

    const size_t SMEM_BYTES = (size_t)SMEM_FLOATS * sizeof(float);
    cudaFuncSetAttribute(gru_persistent, cudaFuncAttributeMaxDynamicSharedMemorySize,
                         (int)SMEM_BYTES);

    transpose_kernel<<<(TT * TB * TI + 255) / 256, 256>>>(x);
    gru_persistent<<<NCTA, NTHR, SMEM_BYTES>>>(W_ih0, W_hh0, b_ih0, b_hh0,
                                               W_ih1, W_hh1, b_ih1, b_hh1,
                                               seqlv, out);
}